// round 9
// baseline (speedup 1.0000x reference)
#include <cuda_runtime.h>
#include <cuda_bf16.h>

#define NKC 5000
#define BB  512
#define TT  100
#define THREADS 256
#define TBL_SLICE 10   // table entries built per block (512*10 >= 5000)

#define BAR_COMPUTE(n) asm volatile("bar.sync 1, %0;" :: "r"(n) : "memory")
#define BAR_COPY(n)    asm volatile("bar.sync 2, %0;" :: "r"(n) : "memory")

__device__ float  g_c4[NKC];   // sigmoid(logits[:,4]) — initial/default state
__device__ float4 g_p4[NKC];   // sigmoid(logits[:,0..3])
__device__ int    g_ready;     // blocks that published their table slice
__device__ int    g_done;      // blocks fully finished (for counter reset)

__device__ __forceinline__ float sigmoidf(float x) {
    return 1.0f / (1.0f + __expf(-x));
}

__global__ __launch_bounds__(THREADS, 4)
void fused_kernel(const int* __restrict__ prev_kc,
                  const int* __restrict__ curr_kc,
                  const int* __restrict__ prev_corr,
                  const float* __restrict__ logits,
                  float* __restrict__ out)
{
    __shared__ int   sPK[TT];
    __shared__ int   sPW[TT];
    __shared__ float sVal[TT];
    __shared__ int   sNotLast[TT];
    __shared__ int   sMaxD;

    const int b   = blockIdx.x;
    const int tid = threadIdx.x;

    float* __restrict__ orow = out + (size_t)BB * TT + (size_t)b * NKC;

    int   pk = -1, ck = -1, c = 0;
    int   pw = -1, w = -1;
    float myVal = 0.f;

    if (tid >= 128) {
        // ================= COPY GROUP (warps 4-7) =================
        // slice build -> arrive -> spin -> bulk copy. Never touches barrier 1.
        if (tid < 128 + TBL_SLICE) {
            const int k = b * TBL_SLICE + (tid - 128);
            if (k < NKC) {
                const float s0 = sigmoidf(logits[k * 5 + 0]);
                const float s1 = sigmoidf(logits[k * 5 + 1]);
                const float s2 = sigmoidf(logits[k * 5 + 2]);
                const float s3 = sigmoidf(logits[k * 5 + 3]);
                const float s4 = sigmoidf(logits[k * 5 + 4]);
                g_p4[k] = make_float4(s0, s1, s2, s3);
                g_c4[k] = s4;
            }
            __threadfence();                   // publish this lane's stores
        }
        __syncwarp();                          // warp 4: builders done
        if (tid == 128)
            atomicAdd(&g_ready, 1);

        // copy-group spinner: warp 5 lane 0 (doesn't delay warp 4's arrive)
        if (tid == 160) {
            while (*(volatile int*)&g_ready < BB)
                __nanosleep(20);
            __threadfence();
        }
        BAR_COPY(128);

        // bulk copy with MLP=10: all loads issued before any store
        {
            const float4* __restrict__ src = (const float4*)g_c4;
            float4*       __restrict__ dst = (float4*)orow;
            const int base = tid - 128;
            float4 v[10];
            #pragma unroll
            for (int u = 0; u < 10; u++) {
                const int i = base + u * 128;
                if (i < NKC / 4) v[u] = src[i];
            }
            #pragma unroll
            for (int u = 0; u < 10; u++) {
                const int i = base + u * 128;
                if (i < NKC / 4) dst[i] = v[u];
            }
        }
    } else {
        // ================= COMPUTE GROUP (warps 0-3) =================
        if (tid == 0) sMaxD = 0;
        if (tid < TT) {
            ck = curr_kc[b * TT + tid];
            pk = prev_kc[b * TT + tid];
            c  = prev_corr[b * TT + tid];
            sPK[tid]      = (tid >= 1) ? pk : -9;   // step 0 performs no update
            sNotLast[tid] = 0;
        }
        BAR_COMPUTE(128);

        // predecessor-only dependency scan (avg 12.5 int4 iters)
        if (tid < TT) {
            const int4* sp4 = (const int4*)sPK;
            const int jmax = tid >> 2;
            for (int j = 0; j <= jmax; j++) {
                const int4 v = sp4[j];
                const int s0 = 4 * j;
                if (v.x == pk && s0     < tid) pw = s0;
                if (v.y == pk && s0 + 1 < tid) pw = s0 + 1;
                if (v.z == pk && s0 + 2 < tid) pw = s0 + 2;
                if (v.w == pk && s0 + 3 < tid) pw = s0 + 3;
                if (v.x == ck && s0     <= tid) w = s0;
                if (v.y == ck && s0 + 1 <= tid) w = s0 + 1;
                if (v.z == ck && s0 + 2 <= tid) w = s0 + 2;
                if (v.w == ck && s0 + 3 <= tid) w = s0 + 3;
            }
            sPW[tid] = pw;
            if (pw >= 0) sNotLast[pw] = 1;     // pw values distinct -> plain store
        }
        BAR_COMPUTE(128);

        // chain depth via pointer chase (depth ~1-4)
        int depth = 0;
        if (tid >= 1 && tid < TT) {
            int j = pw;
            while (j >= 0) { j = sPW[j]; depth++; }
            atomicMax(&sMaxD, depth);
        }

        // compute-group spinner
        if (tid == 0) {
            while (*(volatile int*)&g_ready < BB)
                __nanosleep(20);
            __threadfence();
        }
        BAR_COMPUTE(128);                      // also publishes sMaxD
        const int maxD = sMaxD;

        // table-dependent constants gather
        float A = 0.f, Bc = 0.f, P0 = 0.f, E = 0.f, F = 0.f, G = 0.f;
        float initSkill = 0.f, initCs = 0.f;
        if (tid < TT) {
            const float4 cp = g_p4[ck];
            G = cp.z;
            F = cp.w - cp.z;
            initCs = g_c4[ck];
            if (tid >= 1) {
                const float4 pp = g_p4[pk];
                A  = c ? pp.w : (1.0f - pp.w);    // p_out[:,1]
                Bc = c ? pp.z : (1.0f - pp.z);    // p_out[:,0]
                P0 = pp.x;
                E  = 1.0f - pp.y - pp.x;
                initSkill = g_c4[pk];
            }
        }

        // wavefront by depth: one group barrier per round
        for (int r = 0; r <= maxD; r++) {
            BAR_COMPUTE(128);
            if (tid >= 1 && tid < TT && depth == r) {
                const float skill = (r == 0) ? initSkill : sVal[pw];
                const float num   = A * skill;
                const float den   = fmaf(Bc, -skill, Bc) + num;  // B*(1-skill)+A*skill
                const float filt  = __fdividef(num, den);
                myVal = fmaf(E, filt, P0);
                sVal[tid] = myVal;
            }
        }
        BAR_COMPUTE(128);

        // probs output
        if (tid < TT) {
            const float cs = (w < 0) ? initCs : sVal[w];
            out[b * TT + tid] = fmaf(F, cs, G);
        }
    }

    // ---- join: copy complete + values complete, then sparse patch ----
    __syncthreads();
    if (tid >= 1 && tid < TT && !sNotLast[tid])
        orow[pk] = myVal;

    // ---- counter reset for next graph replay ----
    if (tid == 0) {
        const int d = atomicAdd(&g_done, 1);
        if (d == BB - 1) {          // last block: everyone has passed both spins
            g_ready = 0;
            g_done  = 0;
        }
    }
}

extern "C" void kernel_launch(void* const* d_in, const int* in_sizes, int n_in,
                              void* d_out, int out_size) {
    const int*   prev_kc   = (const int*)d_in[0];
    const int*   curr_kc   = (const int*)d_in[1];
    const int*   prev_corr = (const int*)d_in[2];
    const float* kc_logits = (const float*)d_in[3];
    float*       out       = (float*)d_out;

    fused_kernel<<<BB, THREADS>>>(prev_kc, curr_kc, prev_corr, kc_logits, out);
}